// round 2
// baseline (speedup 1.0000x reference)
#include <cuda_runtime.h>
#include <math.h>

#define Nn 50000
#define Dd 128
#define Tt 4
#define Ee 150000
#define Hh 8
#define ESL (Ee + Nn)       /* edges + self loops per type (GAT) */
#define E4  (Tt * Ee)       /* all HGT edges */
#define NEG_SLOPE 0.2f
#define EPSF 1e-6f

// ---------------- scratch (static device globals; no allocation) ----------------
__device__ float g_h[Nn*Dd];
__device__ float g_xw[Nn*Dd];      // GAT xw / HGT k
__device__ float g_q[Nn*Dd];
__device__ float g_v[Nn*Dd];
__device__ float g_acc[Nn*Dd];
__device__ float g_tmp[Nn*Dd];
__device__ float g_al[Nn*Hh];
__device__ float g_ar[Nn*Hh];
__device__ float g_m[Nn*Hh];
__device__ float g_s[Nn*Hh];
__device__ float g_eatt[E4*Hh];
__device__ float g_qA[Nn*Tt*Dd];   // per-node arel@q
__device__ float g_vM[Nn*Tt*Dd];   // per-node v@mrel

// ---------------- device helpers ----------------
__device__ __forceinline__ float geluf(float x) {
    return 0.5f * x * (1.0f + erff(x * 0.7071067811865476f));
}
__device__ __forceinline__ void atomicMaxF(float* a, float v) {
    if (v >= 0.0f) atomicMax((int*)a, __float_as_int(v));
    else           atomicMin((unsigned int*)a, __float_as_uint(v));
}
__device__ __forceinline__ void red4(float* p, float x, float y, float z, float w) {
    asm volatile("red.global.add.v4.f32 [%0], {%1,%2,%3,%4};"
                 :: "l"(p), "f"(x), "f"(y), "f"(z), "f"(w) : "memory");
}
__device__ __forceinline__ float dot16(const float* __restrict__ a, const float* __restrict__ b) {
    float s = 0.f;
    #pragma unroll
    for (int i = 0; i < 4; i++) {
        float4 x = ((const float4*)a)[i];
        float4 y = ((const float4*)b)[i];
        s += x.x*y.x + x.y*y.y + x.z*y.z + x.w*y.w;
    }
    return s;
}

// ---------------- elementwise ----------------
__global__ void fillk(float* __restrict__ p, float v, int n) {
    int i = blockIdx.x*blockDim.x + threadIdx.x;
    if (i < n) p[i] = v;
}
__global__ void add3k(const float4* __restrict__ a, const float4* __restrict__ b,
                      const float4* __restrict__ c, float4* __restrict__ o, int n4) {
    int i = blockIdx.x*blockDim.x + threadIdx.x;
    if (i < n4) {
        float4 x = a[i], y = b[i], z = c[i];
        o[i] = make_float4(x.x+y.x+z.x, x.y+y.y+z.y, x.z+y.z+z.z, x.w+y.w+z.w);
    }
}
__global__ void geluk(const float* __restrict__ in, float* __restrict__ out, int n) {
    int i = blockIdx.x*blockDim.x + threadIdx.x;
    if (i < n) out[i] = geluf(in[i]);
}

// ---------------- GEMM: C[Mx128] = A[Mx128] @ W[128x128] (+ bias) ----------------
// block = 256 threads, 64 rows x 128 cols per block; thread: 8 rows x 4 cols.
__global__ void gemm128(const float* __restrict__ A, const float* __restrict__ W,
                        const float* __restrict__ bias, float* __restrict__ C, int M) {
    __shared__ float As[64][128];
    const int block_row = blockIdx.x * 64;
    const int tid = threadIdx.x;
    for (int i = tid; i < 64*32; i += 256) {
        int r = i >> 5, c4 = i & 31;
        int gr = block_row + r;
        float4 val = (gr < M) ? *(const float4*)(A + gr*Dd + c4*4) : make_float4(0,0,0,0);
        *(float4*)(&As[r][c4*4]) = val;
    }
    __syncthreads();
    const int tx = tid & 31, ty = tid >> 5;
    const int c = tx * 4;
    float4 acc[8];
    #pragma unroll
    for (int i = 0; i < 8; i++) acc[i] = make_float4(0,0,0,0);
    #pragma unroll 4
    for (int k = 0; k < 128; k++) {
        float4 w = *(const float4*)(W + k*Dd + c);
        #pragma unroll
        for (int i = 0; i < 8; i++) {
            float a = As[ty*8 + i][k];
            acc[i].x += a*w.x; acc[i].y += a*w.y; acc[i].z += a*w.z; acc[i].w += a*w.w;
        }
    }
    float4 b4 = bias ? *(const float4*)(bias + c) : make_float4(0,0,0,0);
    #pragma unroll
    for (int i = 0; i < 8; i++) {
        int gr = block_row + ty*8 + i;
        if (gr < M) {
            float4 o = acc[i];
            o.x += b4.x; o.y += b4.y; o.z += b4.z; o.w += b4.w;
            *(float4*)(C + gr*Dd + c) = o;
        }
    }
}

// ---------------- GAT ----------------
__global__ void alar_k(const float* __restrict__ xw, const float* __restrict__ as,
                       const float* __restrict__ ad, float* __restrict__ al, float* __restrict__ ar) {
    int idx = blockIdx.x*blockDim.x + threadIdx.x;
    if (idx >= Nn*Hh) return;
    int n = idx >> 3, h = idx & 7;
    const float* x  = xw + n*Dd + h*16;
    const float* sp = as + h*16;
    const float* dp = ad + h*16;
    float a = 0.f, r = 0.f;
    #pragma unroll
    for (int j = 0; j < 16; j++) { float v = x[j]; a += v*sp[j]; r += v*dp[j]; }
    al[idx] = a; ar[idx] = r;
}

__global__ void gat_edge_max(const int* __restrict__ ei, const float* __restrict__ al,
                             const float* __restrict__ ar, float* __restrict__ eatt,
                             float* __restrict__ m) {
    int e = blockIdx.x*blockDim.x + threadIdx.x;
    if (e >= ESL) return;
    int src, dst;
    if (e < Ee) { src = ei[e]; dst = ei[Ee + e]; } else { src = dst = e - Ee; }
    const float4* alp = (const float4*)(al + src*8);
    const float4* arp = (const float4*)(ar + dst*8);
    float4 a0 = alp[0], a1 = alp[1], r0 = arp[0], r1 = arp[1];
    float vv[8] = {a0.x+r0.x, a0.y+r0.y, a0.z+r0.z, a0.w+r0.w,
                   a1.x+r1.x, a1.y+r1.y, a1.z+r1.z, a1.w+r1.w};
    #pragma unroll
    for (int h = 0; h < 8; h++) {
        float v = vv[h];
        v = v > 0.f ? v : NEG_SLOPE*v;
        vv[h] = v;
        atomicMaxF(&m[dst*8 + h], v);
    }
    ((float4*)(eatt + e*8))[0] = make_float4(vv[0], vv[1], vv[2], vv[3]);
    ((float4*)(eatt + e*8))[1] = make_float4(vv[4], vv[5], vv[6], vv[7]);
}

__global__ void gat_edge_exp(const int* __restrict__ ei, float* __restrict__ eatt,
                             const float* __restrict__ m, float* __restrict__ s) {
    int e = blockIdx.x*blockDim.x + threadIdx.x;
    if (e >= ESL) return;
    int dst = (e < Ee) ? ei[Ee + e] : (e - Ee);
    float* ep = eatt + e*8;
    const float* mp = m + dst*8;
    #pragma unroll
    for (int h = 0; h < 8; h++) {
        float p = expf(ep[h] - mp[h]);
        ep[h] = p;
        atomicAdd(&s[dst*8 + h], p);
    }
}

__global__ void gat_scatter(const int* __restrict__ ei, const float* __restrict__ eatt,
                            const float* __restrict__ s, const float* __restrict__ xw,
                            float* __restrict__ acc) {
    int gt = blockIdx.x*blockDim.x + threadIdx.x;
    int e = gt >> 5, lane = gt & 31;
    if (e >= ESL) return;
    int src, dst;
    if (e < Ee) { src = ei[e]; dst = ei[Ee + e]; } else { src = dst = e - Ee; }
    int h = lane >> 2;
    float sv = s[dst*8 + h];
    float alpha = eatt[e*8 + h] / (sv > 0.f ? sv : 1.f);
    float4 x = *(const float4*)(xw + src*Dd + lane*4);
    red4(acc + dst*Dd + lane*4, x.x*alpha, x.y*alpha, x.z*alpha, x.w*alpha);
}

// h = gelu(h + rmsnorm(acc + sum_t b[t], g))   (in place on h)
__global__ void gat_post(float* __restrict__ h, const float* __restrict__ acc,
                         const float* __restrict__ b, const float* __restrict__ g) {
    int n = blockIdx.x, d = threadIdx.x;
    float bias = b[d] + b[Dd + d] + b[2*Dd + d] + b[3*Dd + d];
    float a = acc[n*Dd + d] + bias;
    float ss = a*a;
    #pragma unroll
    for (int o = 16; o > 0; o >>= 1) ss += __shfl_xor_sync(0xffffffffu, ss, o);
    __shared__ float sw[4];
    if ((d & 31) == 0) sw[d >> 5] = ss;
    __syncthreads();
    float tot = sw[0] + sw[1] + sw[2] + sw[3];
    float y = g[d] * a * rsqrtf(tot * (1.0f/Dd) + EPSF);
    int i = n*Dd + d;
    h[i] = geluf(h[i] + y);
}

// ---------------- HGT ----------------
// RT=true : o[i] = sum_j R[i*16+j]*x[j]   (qA = arel @ q)
// RT=false: o[i] = sum_j R[j*16+i]*x[j]   (vM = v @ mrel)
template <bool RT>
__global__ void hgt_rel(const float* __restrict__ x, const float* __restrict__ R,
                        float* __restrict__ out) {
    int idx = blockIdx.x*blockDim.x + threadIdx.x;
    if (idx >= Nn*Tt*Hh) return;
    int h = idx & 7, t = (idx >> 3) & 3, n = idx >> 5;
    const float* xp = x + n*Dd + h*16;
    const float* Rp = R + (t*Hh + h)*256;
    float xr[16];
    #pragma unroll
    for (int i = 0; i < 4; i++) ((float4*)xr)[i] = ((const float4*)xp)[i];
    float o[16];
    #pragma unroll
    for (int i = 0; i < 16; i++) o[i] = 0.f;
    #pragma unroll
    for (int j = 0; j < 16; j++) {
        float xj = xr[j];
        #pragma unroll
        for (int i = 0; i < 16; i++)
            o[i] += xj * (RT ? Rp[i*16 + j] : Rp[j*16 + i]);
    }
    float* op = out + (n*Tt + t)*Dd + h*16;
    #pragma unroll
    for (int i = 0; i < 4; i++) ((float4*)op)[i] = ((float4*)o)[i];
}

__device__ __forceinline__ const int* pick_ei(int t, const int* e0, const int* e1,
                                              const int* e2, const int* e3) {
    return (t == 0) ? e0 : (t == 1) ? e1 : (t == 2) ? e2 : e3;
}

__global__ void hgt_att(const int* __restrict__ e0, const int* __restrict__ e1,
                        const int* __restrict__ e2, const int* __restrict__ e3,
                        const float* __restrict__ k, const float* __restrict__ qA,
                        const float* __restrict__ prel, float* __restrict__ eatt,
                        float* __restrict__ m) {
    int idx = blockIdx.x*blockDim.x + threadIdx.x;
    if (idx >= E4*Hh) return;
    int h = idx & 7;
    int ge = idx >> 3;
    int t = ge / Ee, e = ge - t*Ee;
    const int* ei = pick_ei(t, e0, e1, e2, e3);
    int src = ei[e], dst = ei[Ee + e];
    float att = dot16(k + src*Dd + h*16, qA + (dst*Tt + t)*Dd + h*16);
    att *= prel[t*Hh + h] * 0.25f;     // / sqrt(16)
    eatt[idx] = att;
    atomicMaxF(&m[dst*8 + h], att);
}

__global__ void hgt_exp(const int* __restrict__ e0, const int* __restrict__ e1,
                        const int* __restrict__ e2, const int* __restrict__ e3,
                        float* __restrict__ eatt, const float* __restrict__ m,
                        float* __restrict__ s) {
    int ge = blockIdx.x*blockDim.x + threadIdx.x;
    if (ge >= E4) return;
    int t = ge / Ee, e = ge - t*Ee;
    const int* ei = pick_ei(t, e0, e1, e2, e3);
    int dst = ei[Ee + e];
    float* ep = eatt + ge*8;
    const float* mp = m + dst*8;
    #pragma unroll
    for (int h = 0; h < 8; h++) {
        float p = expf(ep[h] - mp[h]);
        ep[h] = p;
        atomicAdd(&s[dst*8 + h], p);
    }
}

__global__ void hgt_scatter(const int* __restrict__ e0, const int* __restrict__ e1,
                            const int* __restrict__ e2, const int* __restrict__ e3,
                            const float* __restrict__ eatt, const float* __restrict__ s,
                            const float* __restrict__ vM, float* __restrict__ acc) {
    int gt = blockIdx.x*blockDim.x + threadIdx.x;
    int ge = gt >> 5, lane = gt & 31;
    if (ge >= E4) return;
    int t = ge / Ee, e = ge - t*Ee;
    const int* ei = pick_ei(t, e0, e1, e2, e3);
    int src = ei[e], dst = ei[Ee + e];
    int h = lane >> 2;
    float sv = s[dst*8 + h];
    float alpha = eatt[ge*8 + h] / (sv > 0.f ? sv : 1.f);
    float4 x = *(const float4*)(vM + (src*Tt + t)*Dd + lane*4);
    red4(acc + dst*Dd + lane*4, x.x*alpha, x.y*alpha, x.z*alpha, x.w*alpha);
}

// out = gelu(h + rmsnorm(beta*o + (1-beta)*h, g)),  beta = sigmoid(skip)
__global__ void hgt_post(const float* __restrict__ h, const float* __restrict__ o,
                         const float* __restrict__ g, const float* __restrict__ skip,
                         float* __restrict__ out) {
    int n = blockIdx.x, d = threadIdx.x;
    float beta = 1.f / (1.f + expf(-skip[0]));
    int i = n*Dd + d;
    float hv = h[i];
    float u = beta*o[i] + (1.f - beta)*hv;
    float ss = u*u;
    #pragma unroll
    for (int off = 16; off > 0; off >>= 1) ss += __shfl_xor_sync(0xffffffffu, ss, off);
    __shared__ float sw[4];
    if ((d & 31) == 0) sw[d >> 5] = ss;
    __syncthreads();
    float tot = sw[0] + sw[1] + sw[2] + sw[3];
    float y = g[d] * u * rsqrtf(tot * (1.0f/Dd) + EPSF);
    out[i] = geluf(hv + y);
}

// ---------------- host launch ----------------
extern "C" void kernel_launch(void* const* d_in, const int* in_sizes, int n_in,
                              void* d_out, int out_size) {
    const float* zL  = (const float*)d_in[0];
    const float* zH  = (const float*)d_in[1];
    const float* xe  = (const float*)d_in[2];
    const float* W1  = (const float*)d_in[3];
    const float* as1 = (const float*)d_in[4];
    const float* ad1 = (const float*)d_in[5];
    const float* b1  = (const float*)d_in[6];
    const float* W2  = (const float*)d_in[7];
    const float* as2 = (const float*)d_in[8];
    const float* ad2 = (const float*)d_in[9];
    const float* b2  = (const float*)d_in[10];
    const float* Wk  = (const float*)d_in[11];
    const float* bk  = (const float*)d_in[12];
    const float* Wq  = (const float*)d_in[13];
    const float* bq  = (const float*)d_in[14];
    const float* Wv  = (const float*)d_in[15];
    const float* bv  = (const float*)d_in[16];
    const float* arel= (const float*)d_in[17];
    const float* mrel= (const float*)d_in[18];
    const float* prel= (const float*)d_in[19];
    const float* Wo  = (const float*)d_in[20];
    const float* bo  = (const float*)d_in[21];
    const float* skip= (const float*)d_in[22];
    const float* g1  = (const float*)d_in[23];
    const float* g2  = (const float*)d_in[24];
    const float* g3  = (const float*)d_in[25];
    const int* ei[4] = {(const int*)d_in[26], (const int*)d_in[27],
                        (const int*)d_in[28], (const int*)d_in[29]};

    float *h_, *xw_, *q_, *v_, *acc_, *tmp_, *al_, *ar_, *m_, *s_, *eatt_, *qA_, *vM_;
    cudaGetSymbolAddress((void**)&h_,   g_h);
    cudaGetSymbolAddress((void**)&xw_,  g_xw);
    cudaGetSymbolAddress((void**)&q_,   g_q);
    cudaGetSymbolAddress((void**)&v_,   g_v);
    cudaGetSymbolAddress((void**)&acc_, g_acc);
    cudaGetSymbolAddress((void**)&tmp_, g_tmp);
    cudaGetSymbolAddress((void**)&al_,  g_al);
    cudaGetSymbolAddress((void**)&ar_,  g_ar);
    cudaGetSymbolAddress((void**)&m_,   g_m);
    cudaGetSymbolAddress((void**)&s_,   g_s);
    cudaGetSymbolAddress((void**)&eatt_,g_eatt);
    cudaGetSymbolAddress((void**)&qA_,  g_qA);
    cudaGetSymbolAddress((void**)&vM_,  g_vM);

    const int nd = Nn*Dd;
    const int nh = Nn*Hh;
    const int TPB = 256;
    const int gemm_grid = (Nn + 63) / 64;

    add3k<<<(nd/4 + TPB-1)/TPB, TPB>>>((const float4*)zL, (const float4*)zH,
                                       (const float4*)xe, (float4*)h_, nd/4);

    // --- two hetero-GAT layers ---
    const float* Ws[2]  = {W1, W2};
    const float* ass[2] = {as1, as2};
    const float* ads[2] = {ad1, ad2};
    const float* bs[2]  = {b1, b2};
    const float* gs[2]  = {g1, g2};
    for (int L = 0; L < 2; L++) {
        fillk<<<(nd + TPB-1)/TPB, TPB>>>(acc_, 0.f, nd);
        for (int t = 0; t < Tt; t++) {
            gemm128<<<gemm_grid, TPB>>>(h_, Ws[L] + t*Dd*Dd, nullptr, xw_, Nn);
            alar_k<<<(nh + TPB-1)/TPB, TPB>>>(xw_, ass[L] + t*Hh*16, ads[L] + t*Hh*16, al_, ar_);
            fillk<<<(nh + TPB-1)/TPB, TPB>>>(m_, -INFINITY, nh);
            fillk<<<(nh + TPB-1)/TPB, TPB>>>(s_, 0.f, nh);
            gat_edge_max<<<(ESL + TPB-1)/TPB, TPB>>>(ei[t], al_, ar_, eatt_, m_);
            gat_edge_exp<<<(ESL + TPB-1)/TPB, TPB>>>(ei[t], eatt_, m_, s_);
            gat_scatter<<<((long)ESL*32 + TPB-1)/TPB, TPB>>>(ei[t], eatt_, s_, xw_, acc_);
        }
        gat_post<<<Nn, Dd>>>(h_, acc_, bs[L], gs[L]);
    }

    // --- HGT layer ---
    gemm128<<<gemm_grid, TPB>>>(h_, Wk, bk, xw_, Nn);   // k
    gemm128<<<gemm_grid, TPB>>>(h_, Wq, bq, q_,  Nn);   // q
    gemm128<<<gemm_grid, TPB>>>(h_, Wv, bv, v_,  Nn);   // v
    hgt_rel<true ><<<(Nn*Tt*Hh + TPB-1)/TPB, TPB>>>(q_, arel, qA_);
    hgt_rel<false><<<(Nn*Tt*Hh + TPB-1)/TPB, TPB>>>(v_, mrel, vM_);
    fillk<<<(nh + TPB-1)/TPB, TPB>>>(m_, -INFINITY, nh);
    fillk<<<(nh + TPB-1)/TPB, TPB>>>(s_, 0.f, nh);
    hgt_att<<<(E4*Hh + TPB-1)/TPB, TPB>>>(ei[0], ei[1], ei[2], ei[3], xw_, qA_, prel, eatt_, m_);
    hgt_exp<<<(E4 + TPB-1)/TPB, TPB>>>(ei[0], ei[1], ei[2], ei[3], eatt_, m_, s_);
    fillk<<<(nd + TPB-1)/TPB, TPB>>>(acc_, 0.f, nd);
    hgt_scatter<<<((long)E4*32 + TPB-1)/TPB, TPB>>>(ei[0], ei[1], ei[2], ei[3], eatt_, s_, vM_, acc_);
    geluk<<<(nd + TPB-1)/TPB, TPB>>>(acc_, tmp_, nd);
    gemm128<<<gemm_grid, TPB>>>(tmp_, Wo, bo, xw_, Nn); // out2
    hgt_post<<<Nn, Dd>>>(h_, xw_, g3, skip, (float*)d_out);
}

// round 3
// speedup vs baseline: 1.1152x; 1.1152x over previous
#include <cuda_runtime.h>
#include <math.h>

#define Nn 50000
#define Dd 128
#define Tt 4
#define Ee 150000
#define Hh 8
#define ESL (Ee + Nn)       /* edges + self loops per type (GAT) */
#define E4  (Tt * Ee)       /* all HGT edges */
#define NEG_SLOPE 0.2f
#define EPSF 1e-6f

// ---------------- scratch (static device globals; no allocation) ----------------
__device__ float g_h[Nn*Dd];
__device__ float g_k[Nn*Dd];
__device__ float g_q[Nn*Dd];
__device__ float g_v[Nn*Dd];
__device__ float g_acc[Nn*Dd];
__device__ float g_tmp[Nn*Dd];
__device__ float g_al[Tt*Nn*Hh];
__device__ float g_ar[Tt*Nn*Hh];
__device__ float g_s[Tt*Nn*Hh];
__device__ float g_big1[(size_t)Tt*Nn*Dd];   // GAT: xw per type | HGT: qA
__device__ float g_big2[(size_t)Tt*Nn*Dd];   // GAT: acc per type | HGT: vM

// ---------------- device helpers ----------------
__device__ __forceinline__ float geluf(float x) {
    return 0.5f * x * (1.0f + erff(x * 0.7071067811865476f));
}
__device__ __forceinline__ void red4(float* p, float x, float y, float z, float w) {
    asm volatile("red.global.add.v4.f32 [%0], {%1,%2,%3,%4};"
                 :: "l"(p), "f"(x), "f"(y), "f"(z), "f"(w) : "memory");
}
__device__ __forceinline__ const int* pick_ei(int t, const int* e0, const int* e1,
                                              const int* e2, const int* e3) {
    return (t == 0) ? e0 : (t == 1) ? e1 : (t == 2) ? e2 : e3;
}

// ---------------- elementwise ----------------
__global__ void fill4k(float4* __restrict__ p, float v, int n4) {
    int i = blockIdx.x*blockDim.x + threadIdx.x;
    if (i < n4) p[i] = make_float4(v, v, v, v);
}
__global__ void add3k(const float4* __restrict__ a, const float4* __restrict__ b,
                      const float4* __restrict__ c, float4* __restrict__ o, int n4) {
    int i = blockIdx.x*blockDim.x + threadIdx.x;
    if (i < n4) {
        float4 x = a[i], y = b[i], z = c[i];
        o[i] = make_float4(x.x+y.x+z.x, x.y+y.y+z.y, x.z+y.z+z.z, x.w+y.w+z.w);
    }
}
// tmp = gelu(acc / s)  (HGT aggregate normalize + gelu)
__global__ void hgt_div_gelu(const float* __restrict__ acc, const float* __restrict__ s,
                             float* __restrict__ out) {
    int i = blockIdx.x*blockDim.x + threadIdx.x;
    if (i >= Nn*Dd) return;
    int n = i >> 7, d = i & 127;
    float sv = s[n*Hh + (d >> 4)];
    out[i] = geluf(acc[i] / (sv > 0.f ? sv : 1.f));
}

// ---------------- GEMM: C[Mx128] = A[Mx128] @ W[128x128] (+ bias) ----------------
// gridDim.y selects weight matrix t. If ALAR: also emit al/ar attention
// coefficients (dot of each output row's 16-dim head chunk with as/ad[t]).
// block = 256 threads, 64 rows x 128 cols per block; thread: 8 rows x 4 cols.
template <bool ALAR>
__global__ void gemm128(const float* __restrict__ A, const float* __restrict__ Wbase,
                        const float* __restrict__ bias, float* __restrict__ Cbase,
                        const float* __restrict__ asb, const float* __restrict__ adb,
                        float* __restrict__ al, float* __restrict__ ar, int M) {
    __shared__ float As[64][128];
    const int t = blockIdx.y;
    const float* W = Wbase + (size_t)t*Dd*Dd;
    float* C = Cbase + (size_t)t*M*Dd;
    const int block_row = blockIdx.x * 64;
    const int tid = threadIdx.x;
    for (int i = tid; i < 64*32; i += 256) {
        int r = i >> 5, c4 = i & 31;
        int gr = block_row + r;
        float4 val = (gr < M) ? *(const float4*)(A + (size_t)gr*Dd + c4*4) : make_float4(0,0,0,0);
        *(float4*)(&As[r][c4*4]) = val;
    }
    __syncthreads();
    const int tx = tid & 31, ty = tid >> 5;
    const int c = tx * 4;
    float4 acc[8];
    #pragma unroll
    for (int i = 0; i < 8; i++) acc[i] = make_float4(0,0,0,0);
    #pragma unroll 4
    for (int k = 0; k < 128; k++) {
        float4 w = *(const float4*)(W + k*Dd + c);
        #pragma unroll
        for (int i = 0; i < 8; i++) {
            float a = As[ty*8 + i][k];
            acc[i].x += a*w.x; acc[i].y += a*w.y; acc[i].z += a*w.z; acc[i].w += a*w.w;
        }
    }
    float4 b4 = bias ? *(const float4*)(bias + c) : make_float4(0,0,0,0);
    #pragma unroll
    for (int i = 0; i < 8; i++) {
        int gr = block_row + ty*8 + i;
        if (gr < M) {
            float4 o = acc[i];
            o.x += b4.x; o.y += b4.y; o.z += b4.z; o.w += b4.w;
            *(float4*)(C + (size_t)gr*Dd + c) = o;
        }
    }
    if (ALAR) {
        // as/ad are [H][16] = 128 floats per type; col c maps to head c>>4.
        float4 s4 = *(const float4*)(asb + t*Dd + c);
        float4 d4 = *(const float4*)(adb + t*Dd + c);
        #pragma unroll
        for (int i = 0; i < 8; i++) {
            float pa = acc[i].x*s4.x + acc[i].y*s4.y + acc[i].z*s4.z + acc[i].w*s4.w;
            float pr = acc[i].x*d4.x + acc[i].y*d4.y + acc[i].z*d4.z + acc[i].w*d4.w;
            pa += __shfl_xor_sync(0xffffffffu, pa, 1);
            pa += __shfl_xor_sync(0xffffffffu, pa, 2);
            pr += __shfl_xor_sync(0xffffffffu, pr, 1);
            pr += __shfl_xor_sync(0xffffffffu, pr, 2);
            int gr = block_row + ty*8 + i;
            if (gr < M && (tx & 3) == 0) {
                int o = ((t*Nn) + gr)*Hh + (tx >> 2);
                al[o] = pa;
                ar[o] = pr;
            }
        }
    }
}

// ---------------- GAT fused edge pass: exp + segment-sum + scatter ----------------
// One warp per (type, edge). Accumulates unnormalized p*x into per-type acc,
// and p into per-type s. Normalization deferred to gat_post.
__global__ void gat_edge(const int* __restrict__ e0, const int* __restrict__ e1,
                         const int* __restrict__ e2, const int* __restrict__ e3,
                         const float* __restrict__ al, const float* __restrict__ ar,
                         const float* __restrict__ xw4, float* __restrict__ s,
                         float* __restrict__ acc4) {
    int gt = blockIdx.x*blockDim.x + threadIdx.x;
    int gw = gt >> 5, lane = gt & 31;
    if (gw >= Tt*ESL) return;
    int t = gw / ESL, e = gw - t*ESL;
    const int* ei = pick_ei(t, e0, e1, e2, e3);
    int src, dst;
    if (e < Ee) { src = ei[e]; dst = ei[Ee + e]; } else { src = dst = e - Ee; }
    float p = 0.f;
    if (lane < Hh) {
        float v = al[(t*Nn + src)*Hh + lane] + ar[(t*Nn + dst)*Hh + lane];
        v = v > 0.f ? v : NEG_SLOPE*v;
        p = expf(v);
        atomicAdd(&s[(t*Nn + dst)*Hh + lane], p);
    }
    float ph = __shfl_sync(0xffffffffu, p, lane >> 2);
    float4 x = *(const float4*)(xw4 + ((size_t)t*Nn + src)*Dd + lane*4);
    red4(acc4 + ((size_t)t*Nn + dst)*Dd + lane*4, x.x*ph, x.y*ph, x.z*ph, x.w*ph);
}

// h = gelu(h + rmsnorm(sum_t(acc4_t / s_t) + sum_t b[t], g))   (in place on h)
__global__ void gat_post(float* __restrict__ h, const float* __restrict__ acc4,
                         const float* __restrict__ s, const float* __restrict__ b,
                         const float* __restrict__ g) {
    int n = blockIdx.x, d = threadIdx.x;
    int hh = d >> 4;
    float a = b[d] + b[Dd + d] + b[2*Dd + d] + b[3*Dd + d];
    #pragma unroll
    for (int t = 0; t < Tt; t++) {
        float sv = s[(t*Nn + n)*Hh + hh];
        a += acc4[((size_t)t*Nn + n)*Dd + d] / (sv > 0.f ? sv : 1.f);
    }
    float ss = a*a;
    #pragma unroll
    for (int o = 16; o > 0; o >>= 1) ss += __shfl_xor_sync(0xffffffffu, ss, o);
    __shared__ float sw[4];
    if ((d & 31) == 0) sw[d >> 5] = ss;
    __syncthreads();
    float tot = sw[0] + sw[1] + sw[2] + sw[3];
    float y = g[d] * a * rsqrtf(tot * (1.0f/Dd) + EPSF);
    int i = n*Dd + d;
    h[i] = geluf(h[i] + y);
}

// ---------------- HGT ----------------
// RT=true : o[i] = sum_j R[i*16+j]*x[j]   (qA = arel @ q)
// RT=false: o[i] = sum_j R[j*16+i]*x[j]   (vM = v @ mrel)
template <bool RT>
__global__ void hgt_rel(const float* __restrict__ x, const float* __restrict__ R,
                        float* __restrict__ out) {
    int idx = blockIdx.x*blockDim.x + threadIdx.x;
    if (idx >= Nn*Tt*Hh) return;
    int h = idx & 7, t = (idx >> 3) & 3, n = idx >> 5;
    const float* xp = x + (size_t)n*Dd + h*16;
    const float* Rp = R + (t*Hh + h)*256;
    float xr[16];
    #pragma unroll
    for (int i = 0; i < 4; i++) ((float4*)xr)[i] = ((const float4*)xp)[i];
    float o[16];
    #pragma unroll
    for (int i = 0; i < 16; i++) o[i] = 0.f;
    #pragma unroll
    for (int j = 0; j < 16; j++) {
        float xj = xr[j];
        #pragma unroll
        for (int i = 0; i < 16; i++)
            o[i] += xj * (RT ? Rp[i*16 + j] : Rp[j*16 + i]);
    }
    float* op = out + ((size_t)n*Tt + t)*Dd + h*16;
    #pragma unroll
    for (int i = 0; i < 4; i++) ((float4*)op)[i] = ((float4*)o)[i];
}

// Fused HGT edge pass: attention dot + exp + segment-sum + message scatter.
// One warp per (type, edge); 4 lanes per head compute the 16-wide dot.
__global__ void hgt_edge(const int* __restrict__ e0, const int* __restrict__ e1,
                         const int* __restrict__ e2, const int* __restrict__ e3,
                         const float* __restrict__ k, const float* __restrict__ qA,
                         const float* __restrict__ prel, const float* __restrict__ vM,
                         float* __restrict__ s, float* __restrict__ acc) {
    int gt = blockIdx.x*blockDim.x + threadIdx.x;
    int gw = gt >> 5, lane = gt & 31;
    if (gw >= E4) return;
    int t = gw / Ee, e = gw - t*Ee;
    const int* ei = pick_ei(t, e0, e1, e2, e3);
    int src = ei[e], dst = ei[Ee + e];
    int h = lane >> 2, qd = lane & 3;
    float4 kv = *(const float4*)(k  + (size_t)src*Dd + h*16 + qd*4);
    float4 qv = *(const float4*)(qA + ((size_t)dst*Tt + t)*Dd + h*16 + qd*4);
    float part = kv.x*qv.x + kv.y*qv.y + kv.z*qv.z + kv.w*qv.w;
    part += __shfl_xor_sync(0xffffffffu, part, 1);
    part += __shfl_xor_sync(0xffffffffu, part, 2);
    float att = part * prel[t*Hh + h] * 0.25f;   // / sqrt(16)
    float p = expf(att);
    if (qd == 0) atomicAdd(&s[dst*Hh + h], p);
    float4 x = *(const float4*)(vM + ((size_t)src*Tt + t)*Dd + lane*4);
    red4(acc + (size_t)dst*Dd + lane*4, x.x*p, x.y*p, x.z*p, x.w*p);
}

// out = gelu(h + rmsnorm(beta*o + (1-beta)*h, g)),  beta = sigmoid(skip)
__global__ void hgt_post(const float* __restrict__ h, const float* __restrict__ o,
                         const float* __restrict__ g, const float* __restrict__ skip,
                         float* __restrict__ out) {
    int n = blockIdx.x, d = threadIdx.x;
    float beta = 1.f / (1.f + expf(-skip[0]));
    int i = n*Dd + d;
    float hv = h[i];
    float u = beta*o[i] + (1.f - beta)*hv;
    float ss = u*u;
    #pragma unroll
    for (int off = 16; off > 0; off >>= 1) ss += __shfl_xor_sync(0xffffffffu, ss, off);
    __shared__ float sw[4];
    if ((d & 31) == 0) sw[d >> 5] = ss;
    __syncthreads();
    float tot = sw[0] + sw[1] + sw[2] + sw[3];
    float y = g[d] * u * rsqrtf(tot * (1.0f/Dd) + EPSF);
    out[i] = geluf(hv + y);
}

// ---------------- host launch ----------------
extern "C" void kernel_launch(void* const* d_in, const int* in_sizes, int n_in,
                              void* d_out, int out_size) {
    const float* zL  = (const float*)d_in[0];
    const float* zH  = (const float*)d_in[1];
    const float* xe  = (const float*)d_in[2];
    const float* W1  = (const float*)d_in[3];
    const float* as1 = (const float*)d_in[4];
    const float* ad1 = (const float*)d_in[5];
    const float* b1  = (const float*)d_in[6];
    const float* W2  = (const float*)d_in[7];
    const float* as2 = (const float*)d_in[8];
    const float* ad2 = (const float*)d_in[9];
    const float* b2  = (const float*)d_in[10];
    const float* Wk  = (const float*)d_in[11];
    const float* bk  = (const float*)d_in[12];
    const float* Wq  = (const float*)d_in[13];
    const float* bq  = (const float*)d_in[14];
    const float* Wv  = (const float*)d_in[15];
    const float* bv  = (const float*)d_in[16];
    const float* arel= (const float*)d_in[17];
    const float* mrel= (const float*)d_in[18];
    const float* prel= (const float*)d_in[19];
    const float* Wo  = (const float*)d_in[20];
    const float* bo  = (const float*)d_in[21];
    const float* skip= (const float*)d_in[22];
    const float* g1  = (const float*)d_in[23];
    const float* g2  = (const float*)d_in[24];
    const float* g3  = (const float*)d_in[25];
    const int* ei[4] = {(const int*)d_in[26], (const int*)d_in[27],
                        (const int*)d_in[28], (const int*)d_in[29]};

    float *h_, *k_, *q_, *v_, *acc_, *tmp_, *al_, *ar_, *s_, *big1_, *big2_;
    cudaGetSymbolAddress((void**)&h_,   g_h);
    cudaGetSymbolAddress((void**)&k_,   g_k);
    cudaGetSymbolAddress((void**)&q_,   g_q);
    cudaGetSymbolAddress((void**)&v_,   g_v);
    cudaGetSymbolAddress((void**)&acc_, g_acc);
    cudaGetSymbolAddress((void**)&tmp_, g_tmp);
    cudaGetSymbolAddress((void**)&al_,  g_al);
    cudaGetSymbolAddress((void**)&ar_,  g_ar);
    cudaGetSymbolAddress((void**)&s_,   g_s);
    cudaGetSymbolAddress((void**)&big1_,g_big1);
    cudaGetSymbolAddress((void**)&big2_,g_big2);

    const int nd = Nn*Dd;
    const int nh = Nn*Hh;
    const int TPB = 256;
    const int gemm_grid = (Nn + 63) / 64;

    add3k<<<(nd/4 + TPB-1)/TPB, TPB>>>((const float4*)zL, (const float4*)zH,
                                       (const float4*)xe, (float4*)h_, nd/4);

    // --- two hetero-GAT layers ---
    const float* Ws[2]  = {W1, W2};
    const float* ass[2] = {as1, as2};
    const float* ads[2] = {ad1, ad2};
    const float* bs[2]  = {b1, b2};
    const float* gs[2]  = {g1, g2};
    for (int L = 0; L < 2; L++) {
        fill4k<<<((size_t)Tt*nd/4 + TPB-1)/TPB, TPB>>>((float4*)big2_, 0.f, Tt*nd/4);
        fill4k<<<(Tt*nh/4 + TPB-1)/TPB, TPB>>>((float4*)s_, 0.f, Tt*nh/4);
        gemm128<true><<<dim3(gemm_grid, Tt), TPB>>>(h_, Ws[L], nullptr, big1_,
                                                    ass[L], ads[L], al_, ar_, Nn);
        gat_edge<<<((size_t)Tt*ESL*32 + TPB-1)/TPB, TPB>>>(ei[0], ei[1], ei[2], ei[3],
                                                           al_, ar_, big1_, s_, big2_);
        gat_post<<<Nn, Dd>>>(h_, big2_, s_, bs[L], gs[L]);
    }

    // --- HGT layer ---
    gemm128<false><<<dim3(gemm_grid,1), TPB>>>(h_, Wk, bk, k_, nullptr, nullptr, nullptr, nullptr, Nn);
    gemm128<false><<<dim3(gemm_grid,1), TPB>>>(h_, Wq, bq, q_, nullptr, nullptr, nullptr, nullptr, Nn);
    gemm128<false><<<dim3(gemm_grid,1), TPB>>>(h_, Wv, bv, v_, nullptr, nullptr, nullptr, nullptr, Nn);
    hgt_rel<true ><<<(Nn*Tt*Hh + TPB-1)/TPB, TPB>>>(q_, arel, big1_);  // qA
    hgt_rel<false><<<(Nn*Tt*Hh + TPB-1)/TPB, TPB>>>(v_, mrel, big2_);  // vM
    fill4k<<<(nh/4 + TPB-1)/TPB, TPB>>>((float4*)s_, 0.f, nh/4);
    fill4k<<<(nd/4 + TPB-1)/TPB, TPB>>>((float4*)acc_, 0.f, nd/4);
    hgt_edge<<<((size_t)E4*32 + TPB-1)/TPB, TPB>>>(ei[0], ei[1], ei[2], ei[3],
                                                   k_, big1_, prel, big2_, s_, acc_);
    hgt_div_gelu<<<(nd + TPB-1)/TPB, TPB>>>(acc_, s_, tmp_);
    gemm128<false><<<dim3(gemm_grid,1), TPB>>>(tmp_, Wo, bo, k_, nullptr, nullptr, nullptr, nullptr, Nn);
    hgt_post<<<Nn, Dd>>>(h_, k_, g3, skip, (float*)d_out);
}